// round 16
// baseline (speedup 1.0000x reference)
#include <cuda_runtime.h>
#include <cuda_bf16.h>
#include <math.h>
#include <stdint.h>

// Problem constants
#define BATCH 4
#define SEQ   2048
#define EMB   1024
#define HEADS 16
#define HDIM  64
#define TOK   (BATCH * SEQ)          // 8192
#define QKVF  (3 * EMB)              // 3072

// Scratch (device globals — no allocation allowed)
__device__ __nv_bfloat16 g_xh[(size_t)TOK * EMB];
__device__ __nv_bfloat16 g_xl[(size_t)TOK * EMB];
__device__ __nv_bfloat16 g_wqkvh[(size_t)QKVF * EMB];
__device__ __nv_bfloat16 g_wqkvl[(size_t)QKVF * EMB];
__device__ __nv_bfloat16 g_wouth[(size_t)EMB * EMB];
__device__ __nv_bfloat16 g_woutl[(size_t)EMB * EMB];
__device__ __nv_bfloat16 g_qkvh[(size_t)TOK * QKVF];
__device__ __nv_bfloat16 g_qkvl[(size_t)TOK * QKVF];
__device__ __nv_bfloat16 g_atth[(size_t)TOK * EMB];
__device__ __nv_bfloat16 g_attl[(size_t)TOK * EMB];

// unified sync array: [0..63] xdone, [64] wqdone, [65] wodone,
// [66..129] rowdone (GEMM1 tiles/rowblock, 48=full), [130..1153] flash flags
#define SY_XD 0
#define SY_WQD 64
#define SY_WOD 65
#define SY_RD 66
#define SY_FL 130
#define SY_TOTAL (130 + 64 * 16)
__device__ int g_sync[SY_TOTAL];

// ---------------------------------------------------------------------------
// PTX helpers — only sm_80+ features (compute_103 baseline safe)
// ---------------------------------------------------------------------------
__device__ __forceinline__ uint32_t smem_u32(const void* p) {
    uint32_t a;
    asm("{ .reg .u64 t; cvta.to.shared.u64 t, %1; cvt.u32.u64 %0, t; }"
        : "=r"(a) : "l"(p));
    return a;
}

#define CP_ASYNC16(dst, src) \
    asm volatile("cp.async.cg.shared.global [%0], [%1], 16;" :: "r"(dst), "l"(src))
#define CP_COMMIT() asm volatile("cp.async.commit_group;")
#define CP_WAIT(n)  asm volatile("cp.async.wait_group %0;" :: "n"(n))

#define LDMATRIX_X4(r0, r1, r2, r3, addr) \
    asm volatile("ldmatrix.sync.aligned.m8n8.x4.shared.b16 {%0,%1,%2,%3}, [%4];" \
                 : "=r"(r0), "=r"(r1), "=r"(r2), "=r"(r3) : "r"(addr))
#define LDMATRIX_X4_T(r0, r1, r2, r3, addr) \
    asm volatile("ldmatrix.sync.aligned.m8n8.x4.trans.shared.b16 {%0,%1,%2,%3}, [%4];" \
                 : "=r"(r0), "=r"(r1), "=r"(r2), "=r"(r3) : "r"(addr))

#define MMA_BF16(c0, c1, c2, c3, a0, a1, a2, a3, b0, b1) \
    asm volatile("mma.sync.aligned.m16n8k16.row.col.f32.bf16.bf16.f32 " \
                 "{%0,%1,%2,%3}, {%4,%5,%6,%7}, {%8,%9}, {%0,%1,%2,%3};" \
                 : "+f"(c0), "+f"(c1), "+f"(c2), "+f"(c3) \
                 : "r"(a0), "r"(a1), "r"(a2), "r"(a3), "r"(b0), "r"(b1))

__device__ __forceinline__ float ex2f(float x) {
    float y;
    asm("ex2.approx.f32 %0, %1;" : "=f"(y) : "f"(x));
    return y;
}

__device__ __forceinline__ uint32_t pack_hi_lo(float a, float b, uint32_t& lo) {
    __nv_bfloat162 h = __floats2bfloat162_rn(a, b);
    float ra = a - __bfloat162float(h.x);
    float rb = b - __bfloat162float(h.y);
    __nv_bfloat162 r = __floats2bfloat162_rn(ra, rb);
    lo = reinterpret_cast<uint32_t&>(r);
    return reinterpret_cast<uint32_t&>(h);
}

// SW128 XOR swizzle on byte offsets (rows of 128B): conflict-free ldmatrix
#define SW128(off) ((uint32_t)(off) ^ ((((uint32_t)(off)) >> 3) & 0x70))

// ---------------------------------------------------------------------------
// MEGA kernel: split + GEMM1 + flash attention + output projection, 5504 CTAs.
//   bids    0..383 : fp32->bf16 hi/lo split (x: 256 CTAs, wq: 96, wo: 32);
//                    bumps xdone[rb] / wqdone / wodone on completion.
//   bids  384..3455: GEMM1 tile (m-major); waits xdone[mb]==4 & wqdone==96;
//                    bumps rowdone[mb].
//   bids 3456..4479: flash tile (qb,h,b); waits rowdone per rowblock;
//                    sets flags[rowblk][h].
//   bids 4480..5503: out-proj; waits wodone==32 once + flags per chunk.
// Deadlock-free: every waiter has a strictly higher bid than its producers.
// ---------------------------------------------------------------------------
#define N4_X  (TOK * EMB / 4)         // 2097152 = 256*8192
#define N4_WQ (QKVF * EMB / 4)        // 786432  = 96*8192
#define N4_WO (EMB * EMB / 4)         // 262144  = 32*8192

#define G_AH 0
#define G_AL 16384
#define G_BH 32768
#define G_BL 40960
#define G_STAGE 49152
#define GM_SMEM (2 * G_STAGE)

#define FA_OFF_QH 0
#define FA_OFF_QL 16384
#define FA_OFF_KV 32768
#define FA_KH 0
#define FA_KL 8192
#define FA_VH 16384
#define FA_VL 24576
#define FA_STAGE 32768
#define FA_OFF_MADD (FA_OFF_KV + 2 * FA_STAGE)   // 98304
#define FA_SMEM (FA_OFF_MADD + 2 * 64 * 4)       // 98816
#define FA_C1 0.18033688011112042f               // 0.125 * log2(e)

__global__ void __launch_bounds__(256, 2) mega_kernel(
    const float4* __restrict__ xf, const float4* __restrict__ wqf,
    const float4* __restrict__ wof,
    __nv_bfloat16* __restrict__ xh, __nv_bfloat16* __restrict__ xl,
    __nv_bfloat16* __restrict__ wqh, __nv_bfloat16* __restrict__ wql,
    __nv_bfloat16* __restrict__ woh, __nv_bfloat16* __restrict__ wol,
    __nv_bfloat16* __restrict__ qkh, __nv_bfloat16* __restrict__ qkl,
    const int* __restrict__ mask,
    __nv_bfloat16* __restrict__ oh, __nv_bfloat16* __restrict__ ol,
    const float* __restrict__ bias, float* __restrict__ out,
    int* __restrict__ sy)
{
    extern __shared__ char sm[];
    const uint32_t smb = smem_u32(sm);
    const int tid = threadIdx.x, wid = tid >> 5, lane = tid & 31;

    if (blockIdx.x < 384) {
        // ===================== SPLIT (fp32 -> bf16 hi/lo) =====================
        const int sbid = blockIdx.x;
        const float4* src;
        __nv_bfloat16 *hd, *ld;
        size_t base;
        if (sbid < 256)      { src = xf;  hd = xh;  ld = xl;  base = (size_t)sbid * 8192; }
        else if (sbid < 352) { src = wqf; hd = wqh; ld = wql; base = (size_t)(sbid - 256) * 8192; }
        else                 { src = wof; hd = woh; ld = wol; base = (size_t)(sbid - 352) * 8192; }

        #pragma unroll 4
        for (int it = 0; it < 32; it++) {
            size_t j = base + it * 256 + tid;
            float4 v = src[j];
            float f[4] = {v.x, v.y, v.z, v.w};
            __nv_bfloat16 h[4], l[4];
            #pragma unroll
            for (int k = 0; k < 4; k++) {
                h[k] = __float2bfloat16(f[k]);
                l[k] = __float2bfloat16(f[k] - __bfloat162float(h[k]));
            }
            ((uint2*)hd)[j] = *(uint2*)h;
            ((uint2*)ld)[j] = *(uint2*)l;
        }
        __syncthreads();
        __threadfence();
        if (tid == 0) {
            if (sbid < 256)      atomicAdd(&sy[SY_XD + (sbid >> 2)], 1);
            else if (sbid < 352) atomicAdd(&sy[SY_WQD], 1);
            else                 atomicAdd(&sy[SY_WOD], 1);
        }

    } else if (blockIdx.x < 3456) {
        // ===================== GEMM1: QKV PROJECTION =====================
        const int bid1 = blockIdx.x - 384;
        const int mb = bid1 / 48;            // rowblock (m-major)
        const int nb = bid1 % 48;
        const int m0 = mb * 128;
        const int n0 = nb * 64;
        const int wm = (wid >> 1) * 32;
        const int wn = (wid & 1) * 32;
        const int N = QKVF, K = EMB;

        auto waitv = [&](int idx, int target) {
            if (tid == 0) {
                while (atomicAdd(&sy[idx], 0) < target) __nanosleep(128);
            }
            __syncthreads();
        };
        waitv(SY_XD + mb, 4);
        waitv(SY_WQD, 96);

        const char* Ahc = (const char*)xh;
        const char* Alc = (const char*)xl;
        const char* Bhc = (const char*)wqh;
        const char* Blc = (const char*)wql;

        auto load_chunk = [&](int k0, int buf) {
            const uint32_t sb = smb + buf * G_STAGE;
            #pragma unroll
            for (int i = 0; i < 8; i++) {
                int idx = tid + i * 256;
                int pl = idx >> 10;
                int r  = (idx >> 3) & 127;
                int c  = (idx & 7) * 16;
                size_t gA = ((size_t)(m0 + r) * K + k0) * 2 + c;
                const char* src = (pl ? Alc : Ahc) + gA;
                CP_ASYNC16(sb + G_AH + pl * 16384 + SW128(r * 128 + c), src);
            }
            #pragma unroll
            for (int i = 0; i < 4; i++) {
                int idx = tid + i * 256;
                int pl = idx >> 9;
                int r  = (idx >> 3) & 63;
                int c  = (idx & 7) * 16;
                size_t gB = ((size_t)(n0 + r) * K + k0) * 2 + c;
                const char* src = (pl ? Blc : Bhc) + gB;
                CP_ASYNC16(sb + G_BH + pl * 8192 + SW128(r * 128 + c), src);
            }
        };

        float acc[2][4][4];
        #pragma unroll
        for (int i = 0; i < 2; i++)
            #pragma unroll
            for (int j = 0; j < 4; j++)
                #pragma unroll
                for (int c = 0; c < 4; c++) acc[i][j][c] = 0.f;

        const int nch = K >> 6;
        load_chunk(0, 0); CP_COMMIT();

        const int a_row  = lane & 15;
        const int a_kofb = (lane >> 4) * 16;
        const int bq     = lane >> 3;
        const int b_row  = (bq >> 1) * 8 + (lane & 7);
        const int b_kofb = (bq & 1) * 16;

        for (int ch = 0; ch < nch; ch++) {
            if (ch + 1 < nch) { load_chunk((ch + 1) << 6, (ch + 1) & 1); CP_COMMIT(); CP_WAIT(1); }
            else              { CP_WAIT(0); }
            __syncthreads();
            const uint32_t sb = smb + (ch & 1) * G_STAGE;

            #pragma unroll
            for (int ks = 0; ks < 4; ks++) {
                const int kb = ks * 32;
                uint32_t bh[4][2], bl[4][2];
                #pragma unroll
                for (int p = 0; p < 2; p++) {
                    uint32_t row = (wn + p * 16 + b_row) * 128;
                    LDMATRIX_X4(bh[2*p][0], bh[2*p][1], bh[2*p+1][0], bh[2*p+1][1],
                                sb + G_BH + SW128(row + kb + b_kofb));
                    LDMATRIX_X4(bl[2*p][0], bl[2*p][1], bl[2*p+1][0], bl[2*p+1][1],
                                sb + G_BL + SW128(row + kb + b_kofb));
                }
                uint32_t ah[2][4], al[2][4];
                #pragma unroll
                for (int mi = 0; mi < 2; mi++) {
                    uint32_t row = (wm + mi * 16 + a_row) * 128;
                    LDMATRIX_X4(ah[mi][0], ah[mi][1], ah[mi][2], ah[mi][3],
                                sb + G_AH + SW128(row + kb + a_kofb));
                    LDMATRIX_X4(al[mi][0], al[mi][1], al[mi][2], al[mi][3],
                                sb + G_AL + SW128(row + kb + a_kofb));
                }
                #pragma unroll
                for (int mi = 0; mi < 2; mi++)
                    #pragma unroll
                    for (int nj = 0; nj < 4; nj++)
                        MMA_BF16(acc[mi][nj][0], acc[mi][nj][1], acc[mi][nj][2], acc[mi][nj][3],
                                 ah[mi][0], ah[mi][1], ah[mi][2], ah[mi][3],
                                 bh[nj][0], bh[nj][1]);
                #pragma unroll
                for (int mi = 0; mi < 2; mi++)
                    #pragma unroll
                    for (int nj = 0; nj < 4; nj++)
                        MMA_BF16(acc[mi][nj][0], acc[mi][nj][1], acc[mi][nj][2], acc[mi][nj][3],
                                 ah[mi][0], ah[mi][1], ah[mi][2], ah[mi][3],
                                 bl[nj][0], bl[nj][1]);
                #pragma unroll
                for (int mi = 0; mi < 2; mi++)
                    #pragma unroll
                    for (int nj = 0; nj < 4; nj++)
                        MMA_BF16(acc[mi][nj][0], acc[mi][nj][1], acc[mi][nj][2], acc[mi][nj][3],
                                 al[mi][0], al[mi][1], al[mi][2], al[mi][3],
                                 bh[nj][0], bh[nj][1]);
            }
            __syncthreads();
        }

        const int g = lane >> 2, t = lane & 3;
        #pragma unroll
        for (int mi = 0; mi < 2; mi++) {
            const int row = m0 + wm + mi * 16 + g;
            #pragma unroll
            for (int nj = 0; nj < 4; nj++) {
                const int col = n0 + wn + nj * 8 + t * 2;
                uint32_t lo0, lo1;
                uint32_t hi0 = pack_hi_lo(acc[mi][nj][0], acc[mi][nj][1], lo0);
                uint32_t hi1 = pack_hi_lo(acc[mi][nj][2], acc[mi][nj][3], lo1);
                *(uint32_t*)(qkh + (size_t)row * N + col)       = hi0;
                *(uint32_t*)(qkl + (size_t)row * N + col)       = lo0;
                *(uint32_t*)(qkh + (size_t)(row + 8) * N + col) = hi1;
                *(uint32_t*)(qkl + (size_t)(row + 8) * N + col) = lo1;
            }
        }

        __syncthreads();
        __threadfence();
        if (tid == 0) atomicAdd(&sy[SY_RD + mb], 1);

    } else if (blockIdx.x < 4480) {
        // ===================== FLASH ATTENTION =====================
        const int bid = blockIdx.x - 3456;
        const int qb = bid & 15, h = (bid >> 4) & 15, b = bid >> 8;
        const int tok0 = b * SEQ + qb * 128;

        const char* qkhc = (const char*)qkh;
        const char* qklc = (const char*)qkl;

        auto wait_row = [&](int rb) {
            if (tid == 0) {
                while (atomicAdd(&sy[SY_RD + rb], 0) < 48) __nanosleep(128);
            }
            __syncthreads();
        };

        auto load_kv = [&](int ch) {
            const uint32_t stg = smb + FA_OFF_KV + (ch & 1) * FA_STAGE;
            const int k0 = ch * 64;
            #pragma unroll
            for (int i = 0; i < 8; i++) {
                int idx = tid + i * 256;
                int tile = idx >> 9;
                int r = (idx >> 3) & 63;
                int c = (idx & 7) * 16;
                size_t gK = ((size_t)(b * SEQ + k0 + r) * QKVF + EMB + h * HDIM) * 2 + c;
                size_t gV = gK + (size_t)EMB * 2;
                const char* src;
                if      (tile == 0) src = qkhc + gK;
                else if (tile == 1) src = qklc + gK;
                else if (tile == 2) src = qkhc + gV;
                else                src = qklc + gV;
                CP_ASYNC16(stg + tile * 8192 + SW128(r * 128 + c), src);
            }
            if (tid < 64) {
                float* md = (float*)(sm + FA_OFF_MADD) + (ch & 1) * 64;
                md[tid] = mask[b * SEQ + k0 + tid] ? 0.f : -1e9f;
            }
        };

        wait_row(b * 16 + qb);
        if (qb != 0) wait_row(b * 16);
        #pragma unroll
        for (int i = 0; i < 8; i++) {
            int idx = tid + i * 256;
            int t2 = idx >> 10;
            int r  = (idx >> 3) & 127;
            int c  = (idx & 7) * 16;
            size_t gb = ((size_t)(tok0 + r) * QKVF + h * HDIM) * 2 + c;
            const char* src = (t2 ? qklc : qkhc) + gb;
            CP_ASYNC16(smb + (t2 ? FA_OFF_QL : FA_OFF_QH) + SW128(r * 128 + c), src);
        }
        load_kv(0);
        CP_COMMIT();

        const int g  = lane >> 2, tq = lane & 3;
        const int a_row = lane & 15, a_kb = (lane >> 4) * 16;
        const int bq = lane >> 3;
        const int b_r = (bq >> 1) * 8 + (lane & 7), b_kb = (bq & 1) * 16;
        const int v_r = (bq & 1) * 8 + (lane & 7),  v_nb = (bq >> 1) * 16;

        float m0r = -1e30f, m1r = -1e30f, l0 = 0.f, l1 = 0.f;
        float o[8][4];
        #pragma unroll
        for (int j = 0; j < 8; j++)
            #pragma unroll
            for (int c = 0; c < 4; c++) o[j][c] = 0.f;

        const int NCH = SEQ / 64;
        for (int ch = 0; ch < NCH; ch++) {
            if (ch + 1 < NCH) {
                if (((ch + 1) & 1) == 0)
                    wait_row(b * 16 + ((ch + 1) >> 1));
                load_kv(ch + 1); CP_COMMIT(); CP_WAIT(1);
            } else {
                CP_WAIT(0);
            }
            __syncthreads();
            const uint32_t stg = smb + FA_OFF_KV + (ch & 1) * FA_STAGE;

            float s[8][4];
            #pragma unroll
            for (int j = 0; j < 8; j++)
                #pragma unroll
                for (int c = 0; c < 4; c++) s[j][c] = 0.f;

            #pragma unroll
            for (int ks = 0; ks < 4; ks++) {
                const int kb = ks * 32;
                uint32_t qh[4], ql[4];
                uint32_t qrow = (wid * 16 + a_row) * 128;
                LDMATRIX_X4(qh[0], qh[1], qh[2], qh[3],
                            smb + FA_OFF_QH + SW128(qrow + kb + a_kb));
                LDMATRIX_X4(ql[0], ql[1], ql[2], ql[3],
                            smb + FA_OFF_QL + SW128(qrow + kb + a_kb));
                uint32_t kh[8][2], kl[8][2];
                #pragma unroll
                for (int p = 0; p < 4; p++) {
                    uint32_t krow = (p * 16 + b_r) * 128;
                    LDMATRIX_X4(kh[2*p][0], kh[2*p][1], kh[2*p+1][0], kh[2*p+1][1],
                                stg + FA_KH + SW128(krow + kb + b_kb));
                    LDMATRIX_X4(kl[2*p][0], kl[2*p][1], kl[2*p+1][0], kl[2*p+1][1],
                                stg + FA_KL + SW128(krow + kb + b_kb));
                }
                #pragma unroll
                for (int j = 0; j < 8; j++)
                    MMA_BF16(s[j][0], s[j][1], s[j][2], s[j][3],
                             qh[0], qh[1], qh[2], qh[3], kh[j][0], kh[j][1]);
                #pragma unroll
                for (int j = 0; j < 8; j++)
                    MMA_BF16(s[j][0], s[j][1], s[j][2], s[j][3],
                             qh[0], qh[1], qh[2], qh[3], kl[j][0], kl[j][1]);
                #pragma unroll
                for (int j = 0; j < 8; j++)
                    MMA_BF16(s[j][0], s[j][1], s[j][2], s[j][3],
                             ql[0], ql[1], ql[2], ql[3], kh[j][0], kh[j][1]);
            }

            const float* md = (const float*)(sm + FA_OFF_MADD) + (ch & 1) * 64;
            #pragma unroll
            for (int j = 0; j < 8; j++) {
                float m0 = md[j * 8 + tq * 2];
                float m1 = md[j * 8 + tq * 2 + 1];
                s[j][0] = fmaf(s[j][0], FA_C1, m0);
                s[j][1] = fmaf(s[j][1], FA_C1, m1);
                s[j][2] = fmaf(s[j][2], FA_C1, m0);
                s[j][3] = fmaf(s[j][3], FA_C1, m1);
            }
            float rm0 = -1e30f, rm1 = -1e30f;
            #pragma unroll
            for (int j = 0; j < 8; j++) {
                rm0 = fmaxf(rm0, fmaxf(s[j][0], s[j][1]));
                rm1 = fmaxf(rm1, fmaxf(s[j][2], s[j][3]));
            }
            rm0 = fmaxf(rm0, __shfl_xor_sync(0xffffffffu, rm0, 1));
            rm0 = fmaxf(rm0, __shfl_xor_sync(0xffffffffu, rm0, 2));
            rm1 = fmaxf(rm1, __shfl_xor_sync(0xffffffffu, rm1, 1));
            rm1 = fmaxf(rm1, __shfl_xor_sync(0xffffffffu, rm1, 2));
            const float mn0 = fmaxf(m0r, rm0);
            const float mn1 = fmaxf(m1r, rm1);
            const float al0 = ex2f(m0r - mn0);
            const float al1 = ex2f(m1r - mn1);
            m0r = mn0; m1r = mn1;

            float rs0 = 0.f, rs1 = 0.f;
            #pragma unroll
            for (int j = 0; j < 8; j++) {
                s[j][0] = ex2f(s[j][0] - mn0);
                s[j][1] = ex2f(s[j][1] - mn0);
                s[j][2] = ex2f(s[j][2] - mn1);
                s[j][3] = ex2f(s[j][3] - mn1);
                rs0 += s[j][0] + s[j][1];
                rs1 += s[j][2] + s[j][3];
            }
            rs0 += __shfl_xor_sync(0xffffffffu, rs0, 1);
            rs0 += __shfl_xor_sync(0xffffffffu, rs0, 2);
            rs1 += __shfl_xor_sync(0xffffffffu, rs1, 1);
            rs1 += __shfl_xor_sync(0xffffffffu, rs1, 2);
            l0 = l0 * al0 + rs0;
            l1 = l1 * al1 + rs1;

            #pragma unroll
            for (int j = 0; j < 8; j++) {
                o[j][0] *= al0; o[j][1] *= al0;
                o[j][2] *= al1; o[j][3] *= al1;
            }

            uint32_t pah[4][4], pal[4][4];
            #pragma unroll
            for (int ks = 0; ks < 4; ks++) {
                const int j0 = 2 * ks, j1 = 2 * ks + 1;
                pah[ks][0] = pack_hi_lo(s[j0][0], s[j0][1], pal[ks][0]);
                pah[ks][1] = pack_hi_lo(s[j0][2], s[j0][3], pal[ks][1]);
                pah[ks][2] = pack_hi_lo(s[j1][0], s[j1][1], pal[ks][2]);
                pah[ks][3] = pack_hi_lo(s[j1][2], s[j1][3], pal[ks][3]);
            }

            #pragma unroll
            for (int ks = 0; ks < 4; ks++) {
                uint32_t vh[4][4], vl[4][4];
                #pragma unroll
                for (int d = 0; d < 4; d++) {
                    uint32_t voff = SW128((ks * 16 + v_r) * 128 + d * 32 + v_nb);
                    LDMATRIX_X4_T(vh[d][0], vh[d][1], vh[d][2], vh[d][3], stg + FA_VH + voff);
                    LDMATRIX_X4_T(vl[d][0], vl[d][1], vl[d][2], vl[d][3], stg + FA_VL + voff);
                }
                #pragma unroll
                for (int d = 0; d < 4; d++) {
                    MMA_BF16(o[2*d][0], o[2*d][1], o[2*d][2], o[2*d][3],
                             pah[ks][0], pah[ks][1], pah[ks][2], pah[ks][3], vh[d][0], vh[d][1]);
                    MMA_BF16(o[2*d+1][0], o[2*d+1][1], o[2*d+1][2], o[2*d+1][3],
                             pah[ks][0], pah[ks][1], pah[ks][2], pah[ks][3], vh[d][2], vh[d][3]);
                }
                #pragma unroll
                for (int d = 0; d < 4; d++) {
                    MMA_BF16(o[2*d][0], o[2*d][1], o[2*d][2], o[2*d][3],
                             pah[ks][0], pah[ks][1], pah[ks][2], pah[ks][3], vl[d][0], vl[d][1]);
                    MMA_BF16(o[2*d+1][0], o[2*d+1][1], o[2*d+1][2], o[2*d+1][3],
                             pah[ks][0], pah[ks][1], pah[ks][2], pah[ks][3], vl[d][2], vl[d][3]);
                }
                #pragma unroll
                for (int d = 0; d < 4; d++) {
                    MMA_BF16(o[2*d][0], o[2*d][1], o[2*d][2], o[2*d][3],
                             pal[ks][0], pal[ks][1], pal[ks][2], pal[ks][3], vh[d][0], vh[d][1]);
                    MMA_BF16(o[2*d+1][0], o[2*d+1][1], o[2*d+1][2], o[2*d+1][3],
                             pal[ks][0], pal[ks][1], pal[ks][2], pal[ks][3], vh[d][2], vh[d][3]);
                }
            }
            __syncthreads();
        }

        const float inv0 = 1.f / l0;
        const float inv1 = 1.f / l1;
        const int r0 = tok0 + wid * 16 + g;
        const int r1 = r0 + 8;
        #pragma unroll
        for (int j = 0; j < 8; j++) {
            const int col = h * HDIM + j * 8 + tq * 2;
            uint32_t lo0, lo1;
            uint32_t hi0 = pack_hi_lo(o[j][0] * inv0, o[j][1] * inv0, lo0);
            uint32_t hi1 = pack_hi_lo(o[j][2] * inv1, o[j][3] * inv1, lo1);
            *(uint32_t*)(oh + (size_t)r0 * EMB + col) = hi0;
            *(uint32_t*)(ol + (size_t)r0 * EMB + col) = lo0;
            *(uint32_t*)(oh + (size_t)r1 * EMB + col) = hi1;
            *(uint32_t*)(ol + (size_t)r1 * EMB + col) = lo1;
        }

        __syncthreads();
        __threadfence();
        if (tid == 0) {
            atomicExch(&sy[SY_FL + (b * 16 + qb) * 16 + h], 1);
        }
    } else {
        // ===================== OUTPUT PROJECTION =====================
        const int bid2 = blockIdx.x - 4480;
        const int n0 = (bid2 & 15) * 64;
        const int mb = bid2 >> 4;
        const int m0 = mb * 128;
        const int wm = (wid >> 1) * 32;
        const int wn = (wid & 1) * 32;
        const int N = EMB, K = EMB;

        const char* Ahc = (const char*)oh;
        const char* Alc = (const char*)ol;
        const char* Bhc = (const char*)woh;
        const char* Blc = (const char*)wol;

        auto waitv = [&](int idx, int target) {
            if (tid == 0) {
                while (atomicAdd(&sy[idx], 0) < target) __nanosleep(128);
            }
            __syncthreads();
        };

        auto load_chunk = [&](int k0, int buf) {
            const uint32_t sb = smb + buf * G_STAGE;
            #pragma unroll
            for (int i = 0; i < 8; i++) {
                int idx = tid + i * 256;
                int pl = idx >> 10;
                int r  = (idx >> 3) & 127;
                int c  = (idx & 7) * 16;
                size_t gA = ((size_t)(m0 + r) * K + k0) * 2 + c;
                const char* src = (pl ? Alc : Ahc) + gA;
                CP_ASYNC16(sb + G_AH + pl * 16384 + SW128(r * 128 + c), src);
            }
            #pragma unroll
            for (int i = 0; i < 4; i++) {
                int idx = tid + i * 256;
                int pl = idx >> 9;
                int r  = (idx >> 3) & 63;
                int c  = (idx & 7) * 16;
                size_t gB = ((size_t)(n0 + r) * K + k0) * 2 + c;
                const char* src = (pl ? Blc : Bhc) + gB;
                CP_ASYNC16(sb + G_BH + pl * 8192 + SW128(r * 128 + c), src);
            }
        };

        float acc[2][4][4];
        #pragma unroll
        for (int i = 0; i < 2; i++)
            #pragma unroll
            for (int j = 0; j < 4; j++)
                #pragma unroll
                for (int c = 0; c < 4; c++) acc[i][j][c] = 0.f;

        const int nch = K >> 6;
        waitv(SY_WOD, 32);                       // w_out split complete
        waitv(SY_FL + mb * 16 + 0, 1);
        load_chunk(0, 0); CP_COMMIT();

        const int a_row  = lane & 15;
        const int a_kofb = (lane >> 4) * 16;
        const int bq     = lane >> 3;
        const int b_row  = (bq >> 1) * 8 + (lane & 7);
        const int b_kofb = (bq & 1) * 16;

        for (int ch = 0; ch < nch; ch++) {
            if (ch + 1 < nch) {
                waitv(SY_FL + mb * 16 + ch + 1, 1);
                load_chunk((ch + 1) << 6, (ch + 1) & 1); CP_COMMIT(); CP_WAIT(1);
            } else {
                CP_WAIT(0);
            }
            __syncthreads();
            const uint32_t sb = smb + (ch & 1) * G_STAGE;

            #pragma unroll
            for (int ks = 0; ks < 4; ks++) {
                const int kb = ks * 32;
                uint32_t bh2[4][2], bl2[4][2];
                #pragma unroll
                for (int p = 0; p < 2; p++) {
                    uint32_t row = (wn + p * 16 + b_row) * 128;
                    LDMATRIX_X4(bh2[2*p][0], bh2[2*p][1], bh2[2*p+1][0], bh2[2*p+1][1],
                                sb + G_BH + SW128(row + kb + b_kofb));
                    LDMATRIX_X4(bl2[2*p][0], bl2[2*p][1], bl2[2*p+1][0], bl2[2*p+1][1],
                                sb + G_BL + SW128(row + kb + b_kofb));
                }
                uint32_t ah[2][4], al[2][4];
                #pragma unroll
                for (int mi = 0; mi < 2; mi++) {
                    uint32_t row = (wm + mi * 16 + a_row) * 128;
                    LDMATRIX_X4(ah[mi][0], ah[mi][1], ah[mi][2], ah[mi][3],
                                sb + G_AH + SW128(row + kb + a_kofb));
                    LDMATRIX_X4(al[mi][0], al[mi][1], al[mi][2], al[mi][3],
                                sb + G_AL + SW128(row + kb + a_kofb));
                }
                #pragma unroll
                for (int mi = 0; mi < 2; mi++)
                    #pragma unroll
                    for (int nj = 0; nj < 4; nj++)
                        MMA_BF16(acc[mi][nj][0], acc[mi][nj][1], acc[mi][nj][2], acc[mi][nj][3],
                                 ah[mi][0], ah[mi][1], ah[mi][2], ah[mi][3],
                                 bh2[nj][0], bh2[nj][1]);
                #pragma unroll
                for (int mi = 0; mi < 2; mi++)
                    #pragma unroll
                    for (int nj = 0; nj < 4; nj++)
                        MMA_BF16(acc[mi][nj][0], acc[mi][nj][1], acc[mi][nj][2], acc[mi][nj][3],
                                 ah[mi][0], ah[mi][1], ah[mi][2], ah[mi][3],
                                 bl2[nj][0], bl2[nj][1]);
                #pragma unroll
                for (int mi = 0; mi < 2; mi++)
                    #pragma unroll
                    for (int nj = 0; nj < 4; nj++)
                        MMA_BF16(acc[mi][nj][0], acc[mi][nj][1], acc[mi][nj][2], acc[mi][nj][3],
                                 al[mi][0], al[mi][1], al[mi][2], al[mi][3],
                                 bh2[nj][0], bh2[nj][1]);
            }
            __syncthreads();
        }

        const int g = lane >> 2, t = lane & 3;
        #pragma unroll
        for (int mi = 0; mi < 2; mi++) {
            const int row = m0 + wm + mi * 16 + g;
            #pragma unroll
            for (int nj = 0; nj < 4; nj++) {
                const int col = n0 + wn + nj * 8 + t * 2;
                float b0 = bias[col], b1 = bias[col + 1];
                float2 v0 = {acc[mi][nj][0] + b0, acc[mi][nj][1] + b1};
                float2 v1 = {acc[mi][nj][2] + b0, acc[mi][nj][3] + b1};
                *(float2*)(out + (size_t)row * N + col)       = v0;
                *(float2*)(out + (size_t)(row + 8) * N + col) = v1;
            }
        }
    }
}

// ---------------------------------------------------------------------------
extern "C" void kernel_launch(void* const* d_in, const int* in_sizes, int n_in,
                              void* d_out, int out_size)
{
    const float* x     = (const float*)d_in[0];
    const float* w_qkv = (const float*)d_in[1];
    const float* w_out = (const float*)d_in[2];
    const float* b_out = (const float*)d_in[3];
    const int*   mask  = (const int*)  d_in[4];
    float* out = (float*)d_out;

    __nv_bfloat16 *xh, *xl, *wqh, *wql, *woh, *wol, *qkh, *qkl, *ath, *atl;
    int* sy;
    cudaGetSymbolAddress((void**)&xh,  g_xh);
    cudaGetSymbolAddress((void**)&xl,  g_xl);
    cudaGetSymbolAddress((void**)&wqh, g_wqkvh);
    cudaGetSymbolAddress((void**)&wql, g_wqkvl);
    cudaGetSymbolAddress((void**)&woh, g_wouth);
    cudaGetSymbolAddress((void**)&wol, g_woutl);
    cudaGetSymbolAddress((void**)&qkh, g_qkvh);
    cudaGetSymbolAddress((void**)&qkl, g_qkvl);
    cudaGetSymbolAddress((void**)&ath, g_atth);
    cudaGetSymbolAddress((void**)&atl, g_attl);
    cudaGetSymbolAddress((void**)&sy,  g_sync);

    cudaFuncSetAttribute((const void*)mega_kernel,
                         cudaFuncAttributeMaxDynamicSharedMemorySize, FA_SMEM);

    // zero all dependency flags, then ONE mega kernel for the whole pipeline
    cudaMemsetAsync(sy, 0, SY_TOTAL * sizeof(int), 0);
    mega_kernel<<<5504, 256, FA_SMEM>>>(
        (const float4*)x, (const float4*)w_qkv, (const float4*)w_out,
        xh, xl, wqh, wql, woh, wol, qkh, qkl, mask, ath, atl,
        b_out, out, sy);
}

// round 17
// speedup vs baseline: 1.0109x; 1.0109x over previous
#include <cuda_runtime.h>
#include <cuda_bf16.h>
#include <math.h>
#include <stdint.h>

// Problem constants
#define BATCH 4
#define SEQ   2048
#define EMB   1024
#define HEADS 16
#define HDIM  64
#define TOK   (BATCH * SEQ)          // 8192
#define QKVF  (3 * EMB)              // 3072

// Scratch (device globals — no allocation allowed)
__device__ __nv_bfloat16 g_xh[(size_t)TOK * EMB];
__device__ __nv_bfloat16 g_xl[(size_t)TOK * EMB];
__device__ __nv_bfloat16 g_wqkvh[(size_t)QKVF * EMB];
__device__ __nv_bfloat16 g_wqkvl[(size_t)QKVF * EMB];
__device__ __nv_bfloat16 g_wouth[(size_t)EMB * EMB];
__device__ __nv_bfloat16 g_woutl[(size_t)EMB * EMB];
__device__ __nv_bfloat16 g_qkvh[(size_t)TOK * QKVF];
__device__ __nv_bfloat16 g_qkvl[(size_t)TOK * QKVF];
__device__ __nv_bfloat16 g_atth[(size_t)TOK * EMB];
__device__ __nv_bfloat16 g_attl[(size_t)TOK * EMB];
__device__ int g_flags[64 * 16];     // flash done: [rowblock(64)][head(16)]
__device__ int g_rowdone[64];        // GEMM1 tiles done per rowblock (48 = full)

// ---------------------------------------------------------------------------
// PTX helpers — only sm_80+ features (compute_103 baseline safe)
// ---------------------------------------------------------------------------
__device__ __forceinline__ uint32_t smem_u32(const void* p) {
    uint32_t a;
    asm("{ .reg .u64 t; cvta.to.shared.u64 t, %1; cvt.u32.u64 %0, t; }"
        : "=r"(a) : "l"(p));
    return a;
}

#define CP_ASYNC16(dst, src) \
    asm volatile("cp.async.cg.shared.global [%0], [%1], 16;" :: "r"(dst), "l"(src))
#define CP_COMMIT() asm volatile("cp.async.commit_group;")
#define CP_WAIT(n)  asm volatile("cp.async.wait_group %0;" :: "n"(n))

#define LDMATRIX_X4(r0, r1, r2, r3, addr) \
    asm volatile("ldmatrix.sync.aligned.m8n8.x4.shared.b16 {%0,%1,%2,%3}, [%4];" \
                 : "=r"(r0), "=r"(r1), "=r"(r2), "=r"(r3) : "r"(addr))
#define LDMATRIX_X4_T(r0, r1, r2, r3, addr) \
    asm volatile("ldmatrix.sync.aligned.m8n8.x4.trans.shared.b16 {%0,%1,%2,%3}, [%4];" \
                 : "=r"(r0), "=r"(r1), "=r"(r2), "=r"(r3) : "r"(addr))

#define MMA_BF16(c0, c1, c2, c3, a0, a1, a2, a3, b0, b1) \
    asm volatile("mma.sync.aligned.m16n8k16.row.col.f32.bf16.bf16.f32 " \
                 "{%0,%1,%2,%3}, {%4,%5,%6,%7}, {%8,%9}, {%0,%1,%2,%3};" \
                 : "+f"(c0), "+f"(c1), "+f"(c2), "+f"(c3) \
                 : "r"(a0), "r"(a1), "r"(a2), "r"(a3), "r"(b0), "r"(b1))

__device__ __forceinline__ float ex2f(float x) {
    float y;
    asm("ex2.approx.f32 %0, %1;" : "=f"(y) : "f"(x));
    return y;
}

__device__ __forceinline__ uint32_t pack_hi_lo(float a, float b, uint32_t& lo) {
    __nv_bfloat162 h = __floats2bfloat162_rn(a, b);
    float ra = a - __bfloat162float(h.x);
    float rb = b - __bfloat162float(h.y);
    __nv_bfloat162 r = __floats2bfloat162_rn(ra, rb);
    lo = reinterpret_cast<uint32_t&>(r);
    return reinterpret_cast<uint32_t&>(h);
}

// SW128 XOR swizzle on byte offsets (rows of 128B): conflict-free ldmatrix
#define SW128(off) ((uint32_t)(off) ^ ((((uint32_t)(off)) >> 3) & 0x70))

// ---------------------------------------------------------------------------
// Fused fp32 -> bf16 hi/lo split for x, w_qkv, w_out; grid-stride
// (standalone launch: split is DRAM-bound and needs high occupancy —
//  folding it into the smem-heavy mega kernel measured +10 us, R16)
// ---------------------------------------------------------------------------
#define N4_X  (TOK * EMB / 4)
#define N4_WQ (QKVF * EMB / 4)
#define N4_WO (EMB * EMB / 4)
#define N4_ALL (N4_X + N4_WQ + N4_WO)

__global__ void __launch_bounds__(256) split3_kernel(
    const float4* __restrict__ x, const float4* __restrict__ wq,
    const float4* __restrict__ wo,
    __nv_bfloat16* __restrict__ xh, __nv_bfloat16* __restrict__ xl,
    __nv_bfloat16* __restrict__ wqh, __nv_bfloat16* __restrict__ wql,
    __nv_bfloat16* __restrict__ woh, __nv_bfloat16* __restrict__ wol)
{
    const int stride = gridDim.x * blockDim.x;
    for (int i = blockIdx.x * blockDim.x + threadIdx.x; i < N4_ALL; i += stride) {
        const float4* src;
        __nv_bfloat16 *hd, *ld;
        int j;
        if (i < N4_X)             { src = x;  hd = xh;  ld = xl;  j = i; }
        else if (i < N4_X + N4_WQ){ src = wq; hd = wqh; ld = wql; j = i - N4_X; }
        else                      { src = wo; hd = woh; ld = wol; j = i - N4_X - N4_WQ; }
        float4 v = src[j];
        float f[4] = {v.x, v.y, v.z, v.w};
        __nv_bfloat16 h[4], l[4];
        #pragma unroll
        for (int k = 0; k < 4; k++) {
            h[k] = __float2bfloat16(f[k]);
            l[k] = __float2bfloat16(f[k] - __bfloat162float(h[k]));
        }
        ((uint2*)hd)[j] = *(uint2*)h;
        ((uint2*)ld)[j] = *(uint2*)l;
    }
}

// ---------------------------------------------------------------------------
// MEGA kernel: GEMM1 + flash attention + output projection, 5120 CTAs (R15).
//   bids    0..3071: GEMM1 tile (m-major: mb = bid/48, nb = bid%48);
//                    bumps rowdone[mb] when its qkv tile is visible.
//   bids 3072..4095: flash tile (qb,h,b); waits rowdone[rb]==48 per rowblock;
//                    sets flags[rowblk][h] when attn tile is visible.
//   bids 4096..5119: out-proj m-block; chunk ch waits flags[mb][ch].
// Deadlock-free: every waiter has a strictly higher bid than its producers.
// ---------------------------------------------------------------------------
#define G_AH 0
#define G_AL 16384
#define G_BH 32768
#define G_BL 40960
#define G_STAGE 49152
#define GM_SMEM (2 * G_STAGE)       // 98304

#define FA_OFF_QH 0
#define FA_OFF_QL 16384
#define FA_OFF_KV 32768
#define FA_KH 0
#define FA_KL 8192
#define FA_VH 16384
#define FA_VL 24576
#define FA_STAGE 32768
#define FA_OFF_MADD (FA_OFF_KV + 2 * FA_STAGE)   // 98304
#define FA_SMEM (FA_OFF_MADD + 2 * 64 * 4)       // 98816  (>= GM_SMEM)
#define FA_C1 0.18033688011112042f               // 0.125 * log2(e)

__global__ void __launch_bounds__(256, 2) mega_kernel(
    const __nv_bfloat16* __restrict__ xh, const __nv_bfloat16* __restrict__ xl,
    const __nv_bfloat16* __restrict__ wqh, const __nv_bfloat16* __restrict__ wql,
    __nv_bfloat16* __restrict__ qkh, __nv_bfloat16* __restrict__ qkl,
    const int* __restrict__ mask,
    __nv_bfloat16* __restrict__ oh, __nv_bfloat16* __restrict__ ol,
    const __nv_bfloat16* __restrict__ Bh, const __nv_bfloat16* __restrict__ Bl,
    const float* __restrict__ bias, float* __restrict__ out,
    int* __restrict__ flags, int* __restrict__ rowdone)
{
    extern __shared__ char sm[];
    const uint32_t smb = smem_u32(sm);
    const int tid = threadIdx.x, wid = tid >> 5, lane = tid & 31;

    if (blockIdx.x < 3072) {
        // ===================== GEMM1: QKV PROJECTION =====================
        const int mb = blockIdx.x / 48;      // rowblock (m-major: finishes in order)
        const int nb = blockIdx.x % 48;
        const int m0 = mb * 128;
        const int n0 = nb * 64;
        const int wm = (wid >> 1) * 32;
        const int wn = (wid & 1) * 32;
        const int N = QKVF, K = EMB;

        const char* Ahc = (const char*)xh;
        const char* Alc = (const char*)xl;
        const char* Bhc = (const char*)wqh;
        const char* Blc = (const char*)wql;

        auto load_chunk = [&](int k0, int buf) {
            const uint32_t sb = smb + buf * G_STAGE;
            #pragma unroll
            for (int i = 0; i < 8; i++) {
                int idx = tid + i * 256;
                int pl = idx >> 10;
                int r  = (idx >> 3) & 127;
                int c  = (idx & 7) * 16;
                size_t gA = ((size_t)(m0 + r) * K + k0) * 2 + c;
                const char* src = (pl ? Alc : Ahc) + gA;
                CP_ASYNC16(sb + G_AH + pl * 16384 + SW128(r * 128 + c), src);
            }
            #pragma unroll
            for (int i = 0; i < 4; i++) {
                int idx = tid + i * 256;
                int pl = idx >> 9;
                int r  = (idx >> 3) & 63;
                int c  = (idx & 7) * 16;
                size_t gB = ((size_t)(n0 + r) * K + k0) * 2 + c;
                const char* src = (pl ? Blc : Bhc) + gB;
                CP_ASYNC16(sb + G_BH + pl * 8192 + SW128(r * 128 + c), src);
            }
        };

        float acc[2][4][4];
        #pragma unroll
        for (int i = 0; i < 2; i++)
            #pragma unroll
            for (int j = 0; j < 4; j++)
                #pragma unroll
                for (int c = 0; c < 4; c++) acc[i][j][c] = 0.f;

        const int nch = K >> 6;
        load_chunk(0, 0); CP_COMMIT();

        const int a_row  = lane & 15;
        const int a_kofb = (lane >> 4) * 16;
        const int bq     = lane >> 3;
        const int b_row  = (bq >> 1) * 8 + (lane & 7);
        const int b_kofb = (bq & 1) * 16;

        for (int ch = 0; ch < nch; ch++) {
            if (ch + 1 < nch) { load_chunk((ch + 1) << 6, (ch + 1) & 1); CP_COMMIT(); CP_WAIT(1); }
            else              { CP_WAIT(0); }
            __syncthreads();
            const uint32_t sb = smb + (ch & 1) * G_STAGE;

            #pragma unroll
            for (int ks = 0; ks < 4; ks++) {
                const int kb = ks * 32;
                uint32_t bh[4][2], bl[4][2];
                #pragma unroll
                for (int p = 0; p < 2; p++) {
                    uint32_t row = (wn + p * 16 + b_row) * 128;
                    LDMATRIX_X4(bh[2*p][0], bh[2*p][1], bh[2*p+1][0], bh[2*p+1][1],
                                sb + G_BH + SW128(row + kb + b_kofb));
                    LDMATRIX_X4(bl[2*p][0], bl[2*p][1], bl[2*p+1][0], bl[2*p+1][1],
                                sb + G_BL + SW128(row + kb + b_kofb));
                }
                uint32_t ah[2][4], al[2][4];
                #pragma unroll
                for (int mi = 0; mi < 2; mi++) {
                    uint32_t row = (wm + mi * 16 + a_row) * 128;
                    LDMATRIX_X4(ah[mi][0], ah[mi][1], ah[mi][2], ah[mi][3],
                                sb + G_AH + SW128(row + kb + a_kofb));
                    LDMATRIX_X4(al[mi][0], al[mi][1], al[mi][2], al[mi][3],
                                sb + G_AL + SW128(row + kb + a_kofb));
                }
                #pragma unroll
                for (int mi = 0; mi < 2; mi++)
                    #pragma unroll
                    for (int nj = 0; nj < 4; nj++)
                        MMA_BF16(acc[mi][nj][0], acc[mi][nj][1], acc[mi][nj][2], acc[mi][nj][3],
                                 ah[mi][0], ah[mi][1], ah[mi][2], ah[mi][3],
                                 bh[nj][0], bh[nj][1]);
                #pragma unroll
                for (int mi = 0; mi < 2; mi++)
                    #pragma unroll
                    for (int nj = 0; nj < 4; nj++)
                        MMA_BF16(acc[mi][nj][0], acc[mi][nj][1], acc[mi][nj][2], acc[mi][nj][3],
                                 ah[mi][0], ah[mi][1], ah[mi][2], ah[mi][3],
                                 bl[nj][0], bl[nj][1]);
                #pragma unroll
                for (int mi = 0; mi < 2; mi++)
                    #pragma unroll
                    for (int nj = 0; nj < 4; nj++)
                        MMA_BF16(acc[mi][nj][0], acc[mi][nj][1], acc[mi][nj][2], acc[mi][nj][3],
                                 al[mi][0], al[mi][1], al[mi][2], al[mi][3],
                                 bh[nj][0], bh[nj][1]);
            }
            __syncthreads();
        }

        const int g = lane >> 2, t = lane & 3;
        #pragma unroll
        for (int mi = 0; mi < 2; mi++) {
            const int row = m0 + wm + mi * 16 + g;
            #pragma unroll
            for (int nj = 0; nj < 4; nj++) {
                const int col = n0 + wn + nj * 8 + t * 2;
                uint32_t lo0, lo1;
                uint32_t hi0 = pack_hi_lo(acc[mi][nj][0], acc[mi][nj][1], lo0);
                uint32_t hi1 = pack_hi_lo(acc[mi][nj][2], acc[mi][nj][3], lo1);
                *(uint32_t*)(qkh + (size_t)row * N + col)       = hi0;
                *(uint32_t*)(qkl + (size_t)row * N + col)       = lo0;
                *(uint32_t*)(qkh + (size_t)(row + 8) * N + col) = hi1;
                *(uint32_t*)(qkl + (size_t)(row + 8) * N + col) = lo1;
            }
        }

        __syncthreads();
        __threadfence();
        if (tid == 0) atomicAdd(&rowdone[mb], 1);

    } else if (blockIdx.x < 4096) {
        // ===================== FLASH ATTENTION =====================
        const int bid = blockIdx.x - 3072;
        const int qb = bid & 15, h = (bid >> 4) & 15, b = bid >> 8;
        const int tok0 = b * SEQ + qb * 128;

        const char* qkhc = (const char*)qkh;
        const char* qklc = (const char*)qkl;

        auto wait_row = [&](int rb) {
            if (tid == 0) {
                while (atomicAdd(&rowdone[rb], 0) < 48) __nanosleep(128);
            }
            __syncthreads();
        };

        auto load_kv = [&](int ch) {
            const uint32_t stg = smb + FA_OFF_KV + (ch & 1) * FA_STAGE;
            const int k0 = ch * 64;
            #pragma unroll
            for (int i = 0; i < 8; i++) {
                int idx = tid + i * 256;
                int tile = idx >> 9;
                int r = (idx >> 3) & 63;
                int c = (idx & 7) * 16;
                size_t gK = ((size_t)(b * SEQ + k0 + r) * QKVF + EMB + h * HDIM) * 2 + c;
                size_t gV = gK + (size_t)EMB * 2;
                const char* src;
                if      (tile == 0) src = qkhc + gK;
                else if (tile == 1) src = qklc + gK;
                else if (tile == 2) src = qkhc + gV;
                else                src = qklc + gV;
                CP_ASYNC16(stg + tile * 8192 + SW128(r * 128 + c), src);
            }
            if (tid < 64) {
                float* md = (float*)(sm + FA_OFF_MADD) + (ch & 1) * 64;
                md[tid] = mask[b * SEQ + k0 + tid] ? 0.f : -1e9f;
            }
        };

        // wait for Q rowblock and KV chunk-0 rowblock, then prologue
        wait_row(b * 16 + qb);
        if (qb != 0) wait_row(b * 16);
        #pragma unroll
        for (int i = 0; i < 8; i++) {
            int idx = tid + i * 256;
            int t2 = idx >> 10;
            int r  = (idx >> 3) & 127;
            int c  = (idx & 7) * 16;
            size_t gb = ((size_t)(tok0 + r) * QKVF + h * HDIM) * 2 + c;
            const char* src = (t2 ? qklc : qkhc) + gb;
            CP_ASYNC16(smb + (t2 ? FA_OFF_QL : FA_OFF_QH) + SW128(r * 128 + c), src);
        }
        load_kv(0);
        CP_COMMIT();

        const int g  = lane >> 2, tq = lane & 3;
        const int a_row = lane & 15, a_kb = (lane >> 4) * 16;
        const int bq = lane >> 3;
        const int b_r = (bq >> 1) * 8 + (lane & 7), b_kb = (bq & 1) * 16;
        const int v_r = (bq & 1) * 8 + (lane & 7),  v_nb = (bq >> 1) * 16;

        float m0r = -1e30f, m1r = -1e30f, l0 = 0.f, l1 = 0.f;
        float o[8][4];
        #pragma unroll
        for (int j = 0; j < 8; j++)
            #pragma unroll
            for (int c = 0; c < 4; c++) o[j][c] = 0.f;

        const int NCH = SEQ / 64;
        for (int ch = 0; ch < NCH; ch++) {
            if (ch + 1 < NCH) {
                if (((ch + 1) & 1) == 0)          // new 128-row GEMM rowblock
                    wait_row(b * 16 + ((ch + 1) >> 1));
                load_kv(ch + 1); CP_COMMIT(); CP_WAIT(1);
            } else {
                CP_WAIT(0);
            }
            __syncthreads();
            const uint32_t stg = smb + FA_OFF_KV + (ch & 1) * FA_STAGE;

            float s[8][4];
            #pragma unroll
            for (int j = 0; j < 8; j++)
                #pragma unroll
                for (int c = 0; c < 4; c++) s[j][c] = 0.f;

            #pragma unroll
            for (int ks = 0; ks < 4; ks++) {
                const int kb = ks * 32;
                uint32_t qh[4], ql[4];
                uint32_t qrow = (wid * 16 + a_row) * 128;
                LDMATRIX_X4(qh[0], qh[1], qh[2], qh[3],
                            smb + FA_OFF_QH + SW128(qrow + kb + a_kb));
                LDMATRIX_X4(ql[0], ql[1], ql[2], ql[3],
                            smb + FA_OFF_QL + SW128(qrow + kb + a_kb));
                uint32_t kh[8][2], kl[8][2];
                #pragma unroll
                for (int p = 0; p < 4; p++) {
                    uint32_t krow = (p * 16 + b_r) * 128;
                    LDMATRIX_X4(kh[2*p][0], kh[2*p][1], kh[2*p+1][0], kh[2*p+1][1],
                                stg + FA_KH + SW128(krow + kb + b_kb));
                    LDMATRIX_X4(kl[2*p][0], kl[2*p][1], kl[2*p+1][0], kl[2*p+1][1],
                                stg + FA_KL + SW128(krow + kb + b_kb));
                }
                #pragma unroll
                for (int j = 0; j < 8; j++)
                    MMA_BF16(s[j][0], s[j][1], s[j][2], s[j][3],
                             qh[0], qh[1], qh[2], qh[3], kh[j][0], kh[j][1]);
                #pragma unroll
                for (int j = 0; j < 8; j++)
                    MMA_BF16(s[j][0], s[j][1], s[j][2], s[j][3],
                             qh[0], qh[1], qh[2], qh[3], kl[j][0], kl[j][1]);
                #pragma unroll
                for (int j = 0; j < 8; j++)
                    MMA_BF16(s[j][0], s[j][1], s[j][2], s[j][3],
                             ql[0], ql[1], ql[2], ql[3], kh[j][0], kh[j][1]);
            }

            const float* md = (const float*)(sm + FA_OFF_MADD) + (ch & 1) * 64;
            #pragma unroll
            for (int j = 0; j < 8; j++) {
                float m0 = md[j * 8 + tq * 2];
                float m1 = md[j * 8 + tq * 2 + 1];
                s[j][0] = fmaf(s[j][0], FA_C1, m0);
                s[j][1] = fmaf(s[j][1], FA_C1, m1);
                s[j][2] = fmaf(s[j][2], FA_C1, m0);
                s[j][3] = fmaf(s[j][3], FA_C1, m1);
            }
            float rm0 = -1e30f, rm1 = -1e30f;
            #pragma unroll
            for (int j = 0; j < 8; j++) {
                rm0 = fmaxf(rm0, fmaxf(s[j][0], s[j][1]));
                rm1 = fmaxf(rm1, fmaxf(s[j][2], s[j][3]));
            }
            rm0 = fmaxf(rm0, __shfl_xor_sync(0xffffffffu, rm0, 1));
            rm0 = fmaxf(rm0, __shfl_xor_sync(0xffffffffu, rm0, 2));
            rm1 = fmaxf(rm1, __shfl_xor_sync(0xffffffffu, rm1, 1));
            rm1 = fmaxf(rm1, __shfl_xor_sync(0xffffffffu, rm1, 2));
            const float mn0 = fmaxf(m0r, rm0);
            const float mn1 = fmaxf(m1r, rm1);
            const float al0 = ex2f(m0r - mn0);
            const float al1 = ex2f(m1r - mn1);
            m0r = mn0; m1r = mn1;

            float rs0 = 0.f, rs1 = 0.f;
            #pragma unroll
            for (int j = 0; j < 8; j++) {
                s[j][0] = ex2f(s[j][0] - mn0);
                s[j][1] = ex2f(s[j][1] - mn0);
                s[j][2] = ex2f(s[j][2] - mn1);
                s[j][3] = ex2f(s[j][3] - mn1);
                rs0 += s[j][0] + s[j][1];
                rs1 += s[j][2] + s[j][3];
            }
            rs0 += __shfl_xor_sync(0xffffffffu, rs0, 1);
            rs0 += __shfl_xor_sync(0xffffffffu, rs0, 2);
            rs1 += __shfl_xor_sync(0xffffffffu, rs1, 1);
            rs1 += __shfl_xor_sync(0xffffffffu, rs1, 2);
            l0 = l0 * al0 + rs0;
            l1 = l1 * al1 + rs1;

            #pragma unroll
            for (int j = 0; j < 8; j++) {
                o[j][0] *= al0; o[j][1] *= al0;
                o[j][2] *= al1; o[j][3] *= al1;
            }

            uint32_t pah[4][4], pal[4][4];
            #pragma unroll
            for (int ks = 0; ks < 4; ks++) {
                const int j0 = 2 * ks, j1 = 2 * ks + 1;
                pah[ks][0] = pack_hi_lo(s[j0][0], s[j0][1], pal[ks][0]);
                pah[ks][1] = pack_hi_lo(s[j0][2], s[j0][3], pal[ks][1]);
                pah[ks][2] = pack_hi_lo(s[j1][0], s[j1][1], pal[ks][2]);
                pah[ks][3] = pack_hi_lo(s[j1][2], s[j1][3], pal[ks][3]);
            }

            #pragma unroll
            for (int ks = 0; ks < 4; ks++) {
                uint32_t vh[4][4], vl[4][4];
                #pragma unroll
                for (int d = 0; d < 4; d++) {
                    uint32_t voff = SW128((ks * 16 + v_r) * 128 + d * 32 + v_nb);
                    LDMATRIX_X4_T(vh[d][0], vh[d][1], vh[d][2], vh[d][3], stg + FA_VH + voff);
                    LDMATRIX_X4_T(vl[d][0], vl[d][1], vl[d][2], vl[d][3], stg + FA_VL + voff);
                }
                #pragma unroll
                for (int d = 0; d < 4; d++) {
                    MMA_BF16(o[2*d][0], o[2*d][1], o[2*d][2], o[2*d][3],
                             pah[ks][0], pah[ks][1], pah[ks][2], pah[ks][3], vh[d][0], vh[d][1]);
                    MMA_BF16(o[2*d+1][0], o[2*d+1][1], o[2*d+1][2], o[2*d+1][3],
                             pah[ks][0], pah[ks][1], pah[ks][2], pah[ks][3], vh[d][2], vh[d][3]);
                }
                #pragma unroll
                for (int d = 0; d < 4; d++) {
                    MMA_BF16(o[2*d][0], o[2*d][1], o[2*d][2], o[2*d][3],
                             pah[ks][0], pah[ks][1], pah[ks][2], pah[ks][3], vl[d][0], vl[d][1]);
                    MMA_BF16(o[2*d+1][0], o[2*d+1][1], o[2*d+1][2], o[2*d+1][3],
                             pah[ks][0], pah[ks][1], pah[ks][2], pah[ks][3], vl[d][2], vl[d][3]);
                }
                #pragma unroll
                for (int d = 0; d < 4; d++) {
                    MMA_BF16(o[2*d][0], o[2*d][1], o[2*d][2], o[2*d][3],
                             pal[ks][0], pal[ks][1], pal[ks][2], pal[ks][3], vh[d][0], vh[d][1]);
                    MMA_BF16(o[2*d+1][0], o[2*d+1][1], o[2*d+1][2], o[2*d+1][3],
                             pal[ks][0], pal[ks][1], pal[ks][2], pal[ks][3], vh[d][2], vh[d][3]);
                }
            }
            __syncthreads();
        }

        const float inv0 = 1.f / l0;
        const float inv1 = 1.f / l1;
        const int r0 = tok0 + wid * 16 + g;
        const int r1 = r0 + 8;
        #pragma unroll
        for (int j = 0; j < 8; j++) {
            const int col = h * HDIM + j * 8 + tq * 2;
            uint32_t lo0, lo1;
            uint32_t hi0 = pack_hi_lo(o[j][0] * inv0, o[j][1] * inv0, lo0);
            uint32_t hi1 = pack_hi_lo(o[j][2] * inv1, o[j][3] * inv1, lo1);
            *(uint32_t*)(oh + (size_t)r0 * EMB + col) = hi0;
            *(uint32_t*)(ol + (size_t)r0 * EMB + col) = lo0;
            *(uint32_t*)(oh + (size_t)r1 * EMB + col) = hi1;
            *(uint32_t*)(ol + (size_t)r1 * EMB + col) = lo1;
        }

        __syncthreads();
        __threadfence();
        if (tid == 0) {
            atomicExch(&flags[(b * 16 + qb) * 16 + h], 1);
        }
    } else {
        // ===================== OUTPUT PROJECTION =====================
        const int bid2 = blockIdx.x - 4096;
        const int n0 = (bid2 & 15) * 64;
        const int mb = bid2 >> 4;
        const int m0 = mb * 128;
        const int wm = (wid >> 1) * 32;
        const int wn = (wid & 1) * 32;
        const int N = EMB, K = EMB;

        const char* Ahc = (const char*)oh;
        const char* Alc = (const char*)ol;
        const char* Bhc = (const char*)Bh;
        const char* Blc = (const char*)Bl;

        auto wait_flag = [&](int ch) {
            if (tid == 0) {
                while (atomicAdd(&flags[mb * 16 + ch], 0) == 0) {
                    __nanosleep(128);
                }
            }
            __syncthreads();
        };

        auto load_chunk = [&](int k0, int buf) {
            const uint32_t sb = smb + buf * G_STAGE;
            #pragma unroll
            for (int i = 0; i < 8; i++) {
                int idx = tid + i * 256;
                int pl = idx >> 10;
                int r  = (idx >> 3) & 127;
                int c  = (idx & 7) * 16;
                size_t gA = ((size_t)(m0 + r) * K + k0) * 2 + c;
                const char* src = (pl ? Alc : Ahc) + gA;
                CP_ASYNC16(sb + G_AH + pl * 16384 + SW128(r * 128 + c), src);
            }
            #pragma unroll
            for (int i = 0; i < 4; i++) {
                int idx = tid + i * 256;
                int pl = idx >> 9;
                int r  = (idx >> 3) & 63;
                int c  = (idx & 7) * 16;
                size_t gB = ((size_t)(n0 + r) * K + k0) * 2 + c;
                const char* src = (pl ? Blc : Bhc) + gB;
                CP_ASYNC16(sb + G_BH + pl * 8192 + SW128(r * 128 + c), src);
            }
        };

        float acc[2][4][4];
        #pragma unroll
        for (int i = 0; i < 2; i++)
            #pragma unroll
            for (int j = 0; j < 4; j++)
                #pragma unroll
                for (int c = 0; c < 4; c++) acc[i][j][c] = 0.f;

        const int nch = K >> 6;
        wait_flag(0);
        load_chunk(0, 0); CP_COMMIT();

        const int a_row  = lane & 15;
        const int a_kofb = (lane >> 4) * 16;
        const int bq     = lane >> 3;
        const int b_row  = (bq >> 1) * 8 + (lane & 7);
        const int b_kofb = (bq & 1) * 16;

        for (int ch = 0; ch < nch; ch++) {
            if (ch + 1 < nch) {
                wait_flag(ch + 1);
                load_chunk((ch + 1) << 6, (ch + 1) & 1); CP_COMMIT(); CP_WAIT(1);
            } else {
                CP_WAIT(0);
            }
            __syncthreads();
            const uint32_t sb = smb + (ch & 1) * G_STAGE;

            #pragma unroll
            for (int ks = 0; ks < 4; ks++) {
                const int kb = ks * 32;
                uint32_t bh2[4][2], bl2[4][2];
                #pragma unroll
                for (int p = 0; p < 2; p++) {
                    uint32_t row = (wn + p * 16 + b_row) * 128;
                    LDMATRIX_X4(bh2[2*p][0], bh2[2*p][1], bh2[2*p+1][0], bh2[2*p+1][1],
                                sb + G_BH + SW128(row + kb + b_kofb));
                    LDMATRIX_X4(bl2[2*p][0], bl2[2*p][1], bl2[2*p+1][0], bl2[2*p+1][1],
                                sb + G_BL + SW128(row + kb + b_kofb));
                }
                uint32_t ah[2][4], al[2][4];
                #pragma unroll
                for (int mi = 0; mi < 2; mi++) {
                    uint32_t row = (wm + mi * 16 + a_row) * 128;
                    LDMATRIX_X4(ah[mi][0], ah[mi][1], ah[mi][2], ah[mi][3],
                                sb + G_AH + SW128(row + kb + a_kofb));
                    LDMATRIX_X4(al[mi][0], al[mi][1], al[mi][2], al[mi][3],
                                sb + G_AL + SW128(row + kb + a_kofb));
                }
                #pragma unroll
                for (int mi = 0; mi < 2; mi++)
                    #pragma unroll
                    for (int nj = 0; nj < 4; nj++)
                        MMA_BF16(acc[mi][nj][0], acc[mi][nj][1], acc[mi][nj][2], acc[mi][nj][3],
                                 ah[mi][0], ah[mi][1], ah[mi][2], ah[mi][3],
                                 bh2[nj][0], bh2[nj][1]);
                #pragma unroll
                for (int mi = 0; mi < 2; mi++)
                    #pragma unroll
                    for (int nj = 0; nj < 4; nj++)
                        MMA_BF16(acc[mi][nj][0], acc[mi][nj][1], acc[mi][nj][2], acc[mi][nj][3],
                                 ah[mi][0], ah[mi][1], ah[mi][2], ah[mi][3],
                                 bl2[nj][0], bl2[nj][1]);
                #pragma unroll
                for (int mi = 0; mi < 2; mi++)
                    #pragma unroll
                    for (int nj = 0; nj < 4; nj++)
                        MMA_BF16(acc[mi][nj][0], acc[mi][nj][1], acc[mi][nj][2], acc[mi][nj][3],
                                 al[mi][0], al[mi][1], al[mi][2], al[mi][3],
                                 bh2[nj][0], bh2[nj][1]);
            }
            __syncthreads();
        }

        const int g = lane >> 2, t = lane & 3;
        #pragma unroll
        for (int mi = 0; mi < 2; mi++) {
            const int row = m0 + wm + mi * 16 + g;
            #pragma unroll
            for (int nj = 0; nj < 4; nj++) {
                const int col = n0 + wn + nj * 8 + t * 2;
                float b0 = bias[col], b1 = bias[col + 1];
                float2 v0 = {acc[mi][nj][0] + b0, acc[mi][nj][1] + b1};
                float2 v1 = {acc[mi][nj][2] + b0, acc[mi][nj][3] + b1};
                *(float2*)(out + (size_t)row * N + col)       = v0;
                *(float2*)(out + (size_t)(row + 8) * N + col) = v1;
            }
        }
    }
}

// ---------------------------------------------------------------------------
extern "C" void kernel_launch(void* const* d_in, const int* in_sizes, int n_in,
                              void* d_out, int out_size)
{
    const float* x     = (const float*)d_in[0];
    const float* w_qkv = (const float*)d_in[1];
    const float* w_out = (const float*)d_in[2];
    const float* b_out = (const float*)d_in[3];
    const int*   mask  = (const int*)  d_in[4];
    float* out = (float*)d_out;

    __nv_bfloat16 *xh, *xl, *wqh, *wql, *woh, *wol, *qkh, *qkl, *ath, *atl;
    int *flags, *rowdone;
    cudaGetSymbolAddress((void**)&xh,  g_xh);
    cudaGetSymbolAddress((void**)&xl,  g_xl);
    cudaGetSymbolAddress((void**)&wqh, g_wqkvh);
    cudaGetSymbolAddress((void**)&wql, g_wqkvl);
    cudaGetSymbolAddress((void**)&woh, g_wouth);
    cudaGetSymbolAddress((void**)&wol, g_woutl);
    cudaGetSymbolAddress((void**)&qkh, g_qkvh);
    cudaGetSymbolAddress((void**)&qkl, g_qkvl);
    cudaGetSymbolAddress((void**)&ath, g_atth);
    cudaGetSymbolAddress((void**)&atl, g_attl);
    cudaGetSymbolAddress((void**)&flags, g_flags);
    cudaGetSymbolAddress((void**)&rowdone, g_rowdone);

    cudaFuncSetAttribute((const void*)mega_kernel,
                         cudaFuncAttributeMaxDynamicSharedMemorySize, FA_SMEM);

    // 0) zero dependency flags + fused splits (standalone: high occupancy)
    cudaMemsetAsync(flags, 0, 64 * 16 * sizeof(int), 0);
    cudaMemsetAsync(rowdone, 0, 64 * sizeof(int), 0);
    split3_kernel<<<6144, 256>>>(
        (const float4*)x, (const float4*)w_qkv, (const float4*)w_out,
        xh, xl, wqh, wql, woh, wol);

    // 1+2+3) MEGA: QKV projection + flash attention + output projection
    mega_kernel<<<5120, 256, FA_SMEM>>>(
        xh, xl, wqh, wql, qkh, qkl, mask, ath, atl,
        woh, wol, b_out, out, flags, rowdone);
}